// round 1
// baseline (speedup 1.0000x reference)
#include <cuda_runtime.h>
#include <math.h>

// ContractiveMessageBlock fused kernel — Round 0 fp32 baseline.
// Structure: [zero accumulators] -> [fused edge kernel: GEMM1+silu+GEMM2(3 chunks)
//            + RBF filter + split + atomic scatter] -> [finalize: mean + transpose]

#define E_TOT   200000
#define FEAT    128
#define TM      64           // edges per block
#define NB      2000         // num CG beads
#define NRBF    20
#define PI_F    3.14159265358979323846f
#define PI_OVER_CUT 0.62831853071795864769f  // pi/5

// SMEM layout (floats):
//   sS   [64][132]  s tile (reused as split0 stash after GEMM1)
//   sH   [64][132]  silu hidden
//   sW   [128][128] W1, then W2 chunks
//   sRbf [64][20]
//   sUnit[64][3]
//   sEnv [64]
//   sBin [64] (int)
#define SM_FLOATS (64*132 + 64*132 + 128*128 + 64*20 + 64*3 + 64 + 64)
#define SMEM_BYTES (SM_FLOATS * 4)

__device__ float g_acc_s[NB * FEAT];      // [bin][f]
__device__ float g_acc_v[NB * 3 * FEAT];  // [bin][x][f]
__device__ float g_cnt[NB];

__global__ void cmb_zero() {
    int i = blockIdx.x * 256 + threadIdx.x;
    if (i < NB * FEAT)     g_acc_s[i] = 0.0f;
    if (i < NB * 3 * FEAT) g_acc_v[i] = 0.0f;
    if (i < NB)            g_cnt[i]   = 0.0f;
}

__global__ void __launch_bounds__(256, 1)
cmb_main(const float* __restrict__ s_i, const float* __restrict__ v_i,
         const float* __restrict__ r_iI, const float* __restrict__ W1,
         const float* __restrict__ b1, const float* __restrict__ W2,
         const float* __restrict__ b2, const float* __restrict__ Wr,
         const float* __restrict__ br, const int* __restrict__ mapping)
{
    extern __shared__ float sm[];
    float* sS    = sm;                     // 64*132
    float* sH    = sS + 64 * 132;          // 64*132
    float* sW    = sH + 64 * 132;          // 128*128
    float* sRbf  = sW + 128 * 128;         // 64*20
    float* sUnit = sRbf + 64 * 20;         // 64*3
    float* sEnv  = sUnit + 64 * 3;         // 64
    int*   sBin  = (int*)(sEnv + 64);      // 64

    const int tid = threadIdx.x;
    const long e0 = (long)blockIdx.x * TM;

    // ---- load s tile [64][128] -> sS (padded stride 132) ----
    {
        const float4* g = (const float4*)(s_i + e0 * FEAT);
        for (int i = tid; i < 64 * 32; i += 256) {
            int e = i >> 5, c = i & 31;
            *(float4*)&sS[e * 132 + c * 4] = g[i];
        }
    }
    // ---- load W1 [128][128] -> sW ----
    {
        const float4* g = (const float4*)W1;
        for (int i = tid; i < 128 * 32; i += 256)
            *(float4*)&sW[i * 4] = g[i];
    }
    // ---- per-edge preprocess: dist/unit/env/rbf/bin/count ----
    if (tid < TM) {
        long eg = e0 + tid;
        float r0 = r_iI[eg * 3 + 0], r1 = r_iI[eg * 3 + 1], r2 = r_iI[eg * 3 + 2];
        float d  = sqrtf(r0 * r0 + r1 * r1 + r2 * r2 + 3e-8f);
        float id = 1.0f / d;
        sUnit[tid * 3 + 0] = r0 * id;
        sUnit[tid * 3 + 1] = r1 * id;
        sUnit[tid * 3 + 2] = r2 * id;
        sEnv[tid] = (d < 5.0f) ? 0.5f * (cosf(PI_OVER_CUT * d) + 1.0f) : 0.0f;
        float ang = PI_OVER_CUT * d;
        #pragma unroll
        for (int n = 0; n < NRBF; n++)
            sRbf[tid * NRBF + n] = sinf((float)(n + 1) * ang) * id;
        int b = mapping[eg];
        sBin[tid] = b;
        atomicAdd(&g_cnt[b], 1.0f);
    }
    __syncthreads();

    const int tx = tid & 31, ty = tid >> 5;
    const int j0 = tx * 4;      // 4 contiguous output cols per thread
    const int eb = ty * 8;      // 8 edges per thread

    // ---- GEMM1: C = s @ W1, 8x4 register tile per thread ----
    float acc[8][4];
    #pragma unroll
    for (int r = 0; r < 8; r++)
        acc[r][0] = acc[r][1] = acc[r][2] = acc[r][3] = 0.0f;

    #pragma unroll 4
    for (int k = 0; k < FEAT; k++) {
        float4 b4 = *(float4*)&sW[k * 128 + j0];
        #pragma unroll
        for (int r = 0; r < 8; r++) {
            float a = sS[(eb + r) * 132 + k];
            acc[r][0] = fmaf(a, b4.x, acc[r][0]);
            acc[r][1] = fmaf(a, b4.y, acc[r][1]);
            acc[r][2] = fmaf(a, b4.z, acc[r][2]);
            acc[r][3] = fmaf(a, b4.w, acc[r][3]);
        }
    }
    // ---- bias + silu -> sH ----
    {
        float4 bb = *(const float4*)&b1[j0];
        #pragma unroll
        for (int r = 0; r < 8; r++) {
            float4 h;
            float x0 = acc[r][0] + bb.x; h.x = x0 / (1.0f + __expf(-x0));
            float x1 = acc[r][1] + bb.y; h.y = x1 / (1.0f + __expf(-x1));
            float x2 = acc[r][2] + bb.z; h.z = x2 / (1.0f + __expf(-x2));
            float x3 = acc[r][3] + bb.w; h.w = x3 / (1.0f + __expf(-x3));
            *(float4*)&sH[(eb + r) * 132 + j0] = h;
        }
    }

    // ---- 3 chunks of GEMM2 (N=128 each) + fused epilogue ----
    for (int c = 0; c < 3; c++) {
        __syncthreads();   // protect sW before overwrite
        for (int i = tid; i < 128 * 32; i += 256) {
            int k = i >> 5, jj = (i & 31) * 4;
            *(float4*)&sW[k * 128 + jj] = *(const float4*)&W2[k * 384 + c * 128 + jj];
        }
        __syncthreads();

        float a2[8][4];
        #pragma unroll
        for (int r = 0; r < 8; r++)
            a2[r][0] = a2[r][1] = a2[r][2] = a2[r][3] = 0.0f;

        #pragma unroll 4
        for (int k = 0; k < FEAT; k++) {
            float4 b4 = *(float4*)&sW[k * 128 + j0];
            #pragma unroll
            for (int r = 0; r < 8; r++) {
                float a = sH[(eb + r) * 132 + k];
                a2[r][0] = fmaf(a, b4.x, a2[r][0]);
                a2[r][1] = fmaf(a, b4.y, a2[r][1]);
                a2[r][2] = fmaf(a, b4.z, a2[r][2]);
                a2[r][3] = fmaf(a, b4.w, a2[r][3]);
            }
        }

        // w_s = (rbf @ Wr + br) * env, per thread for its 8 edges x 4 cols
        float ws[8][4];
        {
            float4 brv = *(const float4*)&br[c * 128 + j0];
            #pragma unroll
            for (int r = 0; r < 8; r++) {
                ws[r][0] = brv.x; ws[r][1] = brv.y; ws[r][2] = brv.z; ws[r][3] = brv.w;
            }
            #pragma unroll
            for (int n = 0; n < NRBF; n++) {
                float4 w4 = *(const float4*)&Wr[n * 384 + c * 128 + j0];
                #pragma unroll
                for (int r = 0; r < 8; r++) {
                    float rb = sRbf[(eb + r) * NRBF + n];
                    ws[r][0] = fmaf(rb, w4.x, ws[r][0]);
                    ws[r][1] = fmaf(rb, w4.y, ws[r][1]);
                    ws[r][2] = fmaf(rb, w4.z, ws[r][2]);
                    ws[r][3] = fmaf(rb, w4.w, ws[r][3]);
                }
            }
        }

        float4 b2v = *(const float4*)&b2[c * 128 + j0];
        #pragma unroll
        for (int r = 0; r < 8; r++) {
            int e = eb + r;
            float envv = sEnv[e];
            float i0 = (a2[r][0] + b2v.x) * (ws[r][0] * envv);
            float i1 = (a2[r][1] + b2v.y) * (ws[r][1] * envv);
            float i2 = (a2[r][2] + b2v.z) * (ws[r][2] * envv);
            float i3 = (a2[r][3] + b2v.w) * (ws[r][3] * envv);

            if (c == 0) {
                // stash split_0 in freed s-tile smem (same thread reads it at c==2)
                sS[e * 132 + j0 + 0] = i0;
                sS[e * 132 + j0 + 1] = i1;
                sS[e * 132 + j0 + 2] = i2;
                sS[e * 132 + j0 + 3] = i3;
            } else if (c == 1) {
                // delta_s scatter
                int bin = sBin[e];
                float* p = &g_acc_s[bin * FEAT + j0];
                atomicAdd(p + 0, i0);
                atomicAdd(p + 1, i1);
                atomicAdd(p + 2, i2);
                atomicAdd(p + 3, i3);
            } else {
                // delta_v = split2 * unit + split0 * v_i, scatter into [bin][x][f]
                int bin = sBin[e];
                long eg = e0 + e;
                float s00 = sS[e * 132 + j0 + 0];
                float s01 = sS[e * 132 + j0 + 1];
                float s02 = sS[e * 132 + j0 + 2];
                float s03 = sS[e * 132 + j0 + 3];
                const float* vg = v_i + ((long)eg * FEAT + j0) * 3;
                #pragma unroll
                for (int x = 0; x < 3; x++) {
                    float u = sUnit[e * 3 + x];
                    float* p = &g_acc_v[bin * 3 * FEAT + x * FEAT + j0];
                    atomicAdd(p + 0, fmaf(i0, u, s00 * vg[0 * 3 + x]));
                    atomicAdd(p + 1, fmaf(i1, u, s01 * vg[1 * 3 + x]));
                    atomicAdd(p + 2, fmaf(i2, u, s02 * vg[2 * 3 + x]));
                    atomicAdd(p + 3, fmaf(i3, u, s03 * vg[3 * 3 + x]));
                }
            }
        }
    }
}

__global__ void cmb_final(float* __restrict__ out) {
    int bin = blockIdx.x;
    int f   = threadIdx.x;
    float ic = 1.0f / fmaxf(g_cnt[bin], 1.0f);
    // delta_s_I : out[0 .. 2000*128)
    out[bin * FEAT + f] = g_acc_s[bin * FEAT + f] * ic;
    // delta_v_I : out[256000 + bin*384 + f*3 + x]  (transpose from [bin][x][f])
    #pragma unroll
    for (int x = 0; x < 3; x++)
        out[NB * FEAT + bin * 384 + f * 3 + x] =
            g_acc_v[bin * 3 * FEAT + x * FEAT + f] * ic;
}

extern "C" void kernel_launch(void* const* d_in, const int* in_sizes, int n_in,
                              void* d_out, int out_size)
{
    const float* s_i     = (const float*)d_in[0];
    const float* v_i     = (const float*)d_in[1];
    const float* r_iI    = (const float*)d_in[2];
    const float* W1      = (const float*)d_in[3];
    const float* b1      = (const float*)d_in[4];
    const float* W2      = (const float*)d_in[5];
    const float* b2      = (const float*)d_in[6];
    const float* Wr      = (const float*)d_in[7];
    const float* br      = (const float*)d_in[8];
    const int*   mapping = (const int*)d_in[9];
    float* out = (float*)d_out;
    (void)in_sizes; (void)n_in; (void)out_size;

    cudaFuncSetAttribute((const void*)cmb_main,
                         cudaFuncAttributeMaxDynamicSharedMemorySize, SMEM_BYTES);

    cmb_zero<<<(NB * 3 * FEAT + 255) / 256, 256>>>();
    cmb_main<<<E_TOT / TM, 256, SMEM_BYTES>>>(s_i, v_i, r_iI, W1, b1, W2, b2,
                                              Wr, br, mapping);
    cmb_final<<<NB, FEAT>>>(out);
}